// round 17
// baseline (speedup 1.0000x reference)
#include <cuda_runtime.h>
#include <cuda_bf16.h>
#include <cuda_fp16.h>
#include <mma.h>
#include <math.h>
#include <cstdint>

using namespace nvcuda;

// Problem constants
#define NODES_MAX 100000
#define EDGES_MAX 3200000
#define D 256
#define NPAD 100224
#define CAP 128                       // padded neighbor capacity per node

// ---------------- scratch (device globals; no runtime allocation) ----------
__device__ __half g_yh[(size_t)NPAD * D];
__device__ __half g_xh[(size_t)NODES_MAX * D];
__device__ __half g_Wh[D * D];
__device__ int   g_colidx[(size_t)NODES_MAX * CAP];
__device__ int   g_pos[NODES_MAX];
__device__ float g_norm[NODES_MAX];
__device__ float g_bcoef[NODES_MAX];

// ---------------- helpers --------------------------------------------------
__device__ __forceinline__ uint32_t smem_u32(const void* p) {
    uint32_t a;
    asm("{ .reg .u64 t; cvta.to.shared.u64 t, %1; cvt.u32.u64 %0, t; }" : "=r"(a) : "l"(p));
    return a;
}
__device__ __forceinline__ void cp16(void* dst, const void* src) {
    uint32_t d = smem_u32(dst);
    asm volatile("cp.async.cg.shared.global [%0], [%1], 16;" :: "r"(d), "l"(src) : "memory");
}
#define CP_COMMIT() asm volatile("cp.async.commit_group;" ::: "memory")
#define CP_WAIT(n)  asm volatile("cp.async.wait_group %0;" :: "n"(n) : "memory")

// ---------------- fused prep: scatter + xhalf + whalf ----------------------
__global__ void k_prep2(const int* __restrict__ rows, const int* __restrict__ cols,
                        const float* __restrict__ x, const float* __restrict__ W,
                        int E, int total4, int SB, int XB) {
    int b = blockIdx.x;
    if (b < SB) {
        int i = b * 256 + threadIdx.x;
        if (i < E) {
            int r = __ldg(rows + i);
            int p = atomicAdd(&g_pos[r], 1);
            if (p < CAP) g_colidx[(size_t)r * CAP + p] = __ldg(cols + i);
        }
    } else if (b < SB + XB) {
        int i = (b - SB) * 256 + threadIdx.x;
        if (i < total4) {
            float4 v = __ldg(&((const float4*)x)[i]);
            __half2 a = __floats2half2_rn(v.x, v.y);
            __half2 c = __floats2half2_rn(v.z, v.w);
            uint2 u;
            u.x = *(uint32_t*)&a;
            u.y = *(uint32_t*)&c;
            *(uint2*)(g_xh + (size_t)i * 4) = u;
        }
    } else {
        int i = (b - SB - XB) * 256 + threadIdx.x;
        if (i < D * D) g_Wh[i] = __float2half_rn(W[i]);
    }
}

__global__ void k_norm(int n) {
    int i = blockIdx.x * blockDim.x + threadIdx.x;
    if (i < n) g_norm[i] = rsqrtf(1.0f + (float)g_pos[i]);
}

// ---------------- per-node gather-reduce (fp16 gather, fp32 self) ----------
__device__ __forceinline__ void acc_half8(float* a, uint4 v, float nc) {
    __half2 h0 = *(__half2*)&v.x, h1 = *(__half2*)&v.y;
    __half2 h2 = *(__half2*)&v.z, h3 = *(__half2*)&v.w;
    float2 f0 = __half22float2(h0), f1 = __half22float2(h1);
    float2 f2 = __half22float2(h2), f3 = __half22float2(h3);
    a[0] = fmaf(nc, f0.x, a[0]); a[1] = fmaf(nc, f0.y, a[1]);
    a[2] = fmaf(nc, f1.x, a[2]); a[3] = fmaf(nc, f1.y, a[3]);
    a[4] = fmaf(nc, f2.x, a[4]); a[5] = fmaf(nc, f2.y, a[5]);
    a[6] = fmaf(nc, f3.x, a[6]); a[7] = fmaf(nc, f3.y, a[7]);
}

__global__ void k_aggregate(const float* __restrict__ x, int n) {
    int gw   = (blockIdx.x * blockDim.x + threadIdx.x) >> 5;
    int lane = threadIdx.x & 31;
    if (gw >= n) return;
    int i   = gw;
    int deg = g_pos[i];
    if (deg > CAP) deg = CAP;
    int beg = i * CAP;
    int end = beg + deg;

    float a[8] = {0.f, 0.f, 0.f, 0.f, 0.f, 0.f, 0.f, 0.f};
    float s = 0.f;

    int j = beg;
    for (; j + 1 < end; j += 2) {
        int   c0 = __ldg(&g_colidx[j]);
        int   c1 = __ldg(&g_colidx[j + 1]);
        float n0 = __ldg(&g_norm[c0]);
        float n1 = __ldg(&g_norm[c1]);
        uint4 v0 = __ldg((const uint4*)(g_xh + (size_t)c0 * D) + lane);
        uint4 v1 = __ldg((const uint4*)(g_xh + (size_t)c1 * D) + lane);
        s += n0 + n1;
        acc_half8(a, v0, n0);
        acc_half8(a, v1, n1);
    }
    if (j < end) {
        int   c  = __ldg(&g_colidx[j]);
        float nc = __ldg(&g_norm[c]);
        s += nc;
        uint4 v = __ldg((const uint4*)(g_xh + (size_t)c * D) + lane);
        acc_half8(a, v, nc);
    }

    float ni = g_norm[i];
    float c2 = ni * ni;
    const float4* xi = (const float4*)(x + (size_t)i * D + 8 * lane);
    float4 s0 = __ldg(&xi[0]);
    float4 s1 = __ldg(&xi[1]);

    float y0 = fmaf(ni, a[0], c2 * s0.x), y1 = fmaf(ni, a[1], c2 * s0.y);
    float y2 = fmaf(ni, a[2], c2 * s0.z), y3 = fmaf(ni, a[3], c2 * s0.w);
    float y4 = fmaf(ni, a[4], c2 * s1.x), y5 = fmaf(ni, a[5], c2 * s1.y);
    float y6 = fmaf(ni, a[6], c2 * s1.z), y7 = fmaf(ni, a[7], c2 * s1.w);

    __half2 p0 = __floats2half2_rn(y0, y1);
    __half2 p1 = __floats2half2_rn(y2, y3);
    __half2 p2 = __floats2half2_rn(y4, y5);
    __half2 p3 = __floats2half2_rn(y6, y7);
    uint4 u;
    u.x = *(uint32_t*)&p0; u.y = *(uint32_t*)&p1;
    u.z = *(uint32_t*)&p2; u.w = *(uint32_t*)&p3;
    *(uint4*)(g_yh + (size_t)i * D + 8 * lane) = u;
    if (lane == 0) g_bcoef[i] = ni * (s + ni);
}

// ---------------- WMMA GEMM v3: 128x64 block tile, 32x32 warp tile ---------
// 8 warps (4 along M x 2 along N). acc = 4 fragments (32 regs) -> 3 CTAs/SM.
#define GBM 128
#define GBN 64
#define GBK 32
#define NST 8
#define TS 40
#define TILE_A (128 * TS * 2)          // 10240 B
#define TILE_B (64 * TS * 2)           // 5120 B
#define STG_LD 68
#define SMEM_BIAS 0
#define SMEM_TILES 512
// layout: A0@512 B0@10752 A1@15872 B1@26112 (end 31232); stg aliased @512 (34816)
#define GEMM_SMEM (512 + 128 * STG_LD * 4)   // 512 + 34816 = 35328

__global__ __launch_bounds__(256, 3) void k_gemm_wmma(const float* __restrict__ bias,
                                                      float* __restrict__ out, int M) {
    extern __shared__ char sm[];
    float* s_bias = (float*)(sm + SMEM_BIAS);
    char*  tiles  = sm + SMEM_TILES;
    __half* Abuf[2] = {(__half*)(tiles),                   (__half*)(tiles + TILE_A + TILE_B)};
    __half* Bbuf[2] = {(__half*)(tiles + TILE_A),          (__half*)(tiles + 2 * TILE_A + TILE_B)};
    float* stg = (float*)tiles;

    int tid = threadIdx.x;
    int wid = tid >> 5;
    int wm  = wid & 3;                 // 4 warps along M (32 rows each)
    int wn  = wid >> 2;                // 2 warps along N (32 cols each)
    int bn  = blockIdx.x * GBN;
    int bm  = blockIdx.y * GBM;

    if (tid < 64) s_bias[tid] = bias[bn + tid];

    wmma::fragment<wmma::accumulator, 16, 16, 16, float> acc[2][2];
#pragma unroll
    for (int i = 0; i < 2; i++)
#pragma unroll
        for (int jj = 0; jj < 2; jj++) wmma::fill_fragment(acc[i][jj], 0.f);

    auto issue = [&](int c) {
        int kk = c * GBK;
        __half* Ad = Abuf[c & 1];
        __half* Bd = Bbuf[c & 1];
        // A tile: 128 rows x 32 halves = 512 16B chunks -> 2 per thread
#pragma unroll
        for (int r = 0; r < 2; r++) {
            int u   = tid + r * 256;
            int row = u >> 2;
            int c8  = (u & 3) * 8;
            cp16(Ad + row * TS + c8, g_yh + (size_t)(bm + row) * D + kk + c8);
        }
        // B tile: 64 rows x 32 halves = 256 chunks -> 1 per thread
        {
            int row = tid >> 2;
            int c8  = (tid & 3) * 8;
            cp16(Bbuf[c & 1] + row * TS + c8, g_Wh + (size_t)(bn + row) * D + kk + c8);
            (void)Bd;
        }
    };

    issue(0);
    CP_COMMIT();
    for (int c = 0; c < NST; c++) {
        if (c + 1 < NST) { issue(c + 1); CP_COMMIT(); CP_WAIT(1); }
        else             { CP_WAIT(0); }
        __syncthreads();

        const __half* As = Abuf[c & 1];
        const __half* Bs = Bbuf[c & 1];
#pragma unroll
        for (int ks = 0; ks < GBK; ks += 16) {
            wmma::fragment<wmma::matrix_a, 16, 16, 16, __half, wmma::row_major> af[2];
#pragma unroll
            for (int i = 0; i < 2; i++)
                wmma::load_matrix_sync(af[i], As + (wm * 32 + i * 16) * TS + ks, TS);
#pragma unroll
            for (int jj = 0; jj < 2; jj++) {
                wmma::fragment<wmma::matrix_b, 16, 16, 16, __half, wmma::col_major> bf;
                wmma::load_matrix_sync(bf, Bs + (wn * 32 + jj * 16) * TS + ks, TS);
#pragma unroll
                for (int i = 0; i < 2; i++)
                    wmma::mma_sync(acc[i][jj], af[i], bf, acc[i][jj]);
            }
        }
        __syncthreads();
    }

#pragma unroll
    for (int i = 0; i < 2; i++)
#pragma unroll
        for (int jj = 0; jj < 2; jj++)
            wmma::store_matrix_sync(stg + (size_t)(wm * 32 + i * 16) * STG_LD + wn * 32 + jj * 16,
                                    acc[i][jj], STG_LD, wmma::mem_row_major);
    __syncthreads();

    int row  = tid >> 1;              // 0..127
    int half = tid & 1;               // 0..1 -> 32 cols each
    int m    = bm + row;
    if (m < M) {
        float bc = g_bcoef[m];
        const float* sr = stg + (size_t)row * STG_LD + half * 32;
        float*       op = out + (size_t)m * D + bn + half * 32;
        const float* bl = s_bias + half * 32;
#pragma unroll
        for (int q = 0; q < 8; q++) {
            float4 v;
            v.x = sr[4 * q + 0] + bc * bl[4 * q + 0];
            v.y = sr[4 * q + 1] + bc * bl[4 * q + 1];
            v.z = sr[4 * q + 2] + bc * bl[4 * q + 2];
            v.w = sr[4 * q + 3] + bc * bl[4 * q + 3];
            *(float4*)(op + 4 * q) = v;
        }
    }
}

// ------------------------------------------------------------- entry point
extern "C" void kernel_launch(void* const* d_in, const int* in_sizes, int n_in,
                              void* d_out, int out_size) {
    const float* x    = (const float*)d_in[0];
    const float* W    = (const float*)d_in[1];
    const float* bias = (const float*)d_in[2];
    const int*   rows = (const int*)d_in[3];
    const int*   cols = (const int*)d_in[4];
    int N = in_sizes[0] / D;
    int E = in_sizes[3];
    if (N > NODES_MAX) N = NODES_MAX;
    if (E > EDGES_MAX) E = EDGES_MAX;

    cudaFuncSetAttribute(k_gemm_wmma, cudaFuncAttributeMaxDynamicSharedMemorySize, GEMM_SMEM);

    void* posPtr = nullptr;
    cudaGetSymbolAddress(&posPtr, g_pos);
    cudaMemsetAsync(posPtr, 0, (size_t)N * sizeof(int));

    int total4 = N * D / 4;
    int SB = (E + 255) / 256;
    int XB = (total4 + 255) / 256;
    int WB = (D * D + 255) / 256;

    k_prep2<<<SB + XB + WB, 256>>>(rows, cols, x, W, E, total4, SB, XB);
    k_norm<<<(N + 255) / 256, 256>>>(N);
    k_aggregate<<<(N * 32 + 255) / 256, 256>>>(x, N);
    dim3 grid(D / GBN, (N + GBM - 1) / GBM);
    k_gemm_wmma<<<grid, 256, GEMM_SMEM>>>(bias, (float*)d_out, N);
}